// round 12
// baseline (speedup 1.0000x reference)
#include <cuda_runtime.h>
#include <cuda_fp16.h>
#include <math.h>
#include <stdint.h>

// B=4,H=16 -> BH=64; S=1024; D=64; rel-pos P=32
#define BH   64
#define SEQ  1024
#define DH   64
#define NTHR 256
#define NROW 64
#define ISD  0.125f
#define NEGINF (-INFINITY)

#define PST_STR 132     // p-stage stride (floats; 528B, 16B-divisible)
#define QSTG_STR 68     // fp32 Q staging stride

// smem layout (bytes) — only p-stage + tables now
#define OFF_PST  0                       // p stage f32 [64][132] 33792
                                         //  (preamble: Q f32 [64][68] @0 + pe_k @+17408)
                                         //  (tail: taps @0, l @+8704, inv @+9216, OX @+9472)
#define OFF_QPE  33792                   // qpe [64][34] f32     8704
#define OFF_PEV  42496                   // pe_v [33][66] f32    8712
#define OFF_M    51208                   // M bound [64]          256
#define SMEM_TOTAL 51464

// fragment-ordered operand arrays: [bh][kt][half][ks][b][lane][nt]  (uint32 = half2)
__device__ __align__(16) uint32_t g_Kf[(size_t)BH * 8 * 4096];
__device__ __align__(16) uint32_t g_Vf[(size_t)BH * 8 * 4096];
__device__ unsigned int g_maxkq[BH];    // max ||k_row||^2 bits (atomicMax, idempotent)

static __device__ __forceinline__ uint32_t h2u(float a, float b) {
    __half2 h = __floats2half2_rn(a, b);
    return *reinterpret_cast<uint32_t*>(&h);
}
static __device__ __forceinline__ void mma16(float* d, const uint32_t* a,
                                             uint32_t b0, uint32_t b1) {
    asm volatile("mma.sync.aligned.m16n8k16.row.col.f32.f16.f16.f32 "
        "{%0,%1,%2,%3},{%4,%5,%6,%7},{%8,%9},{%0,%1,%2,%3};"
        : "+f"(d[0]), "+f"(d[1]), "+f"(d[2]), "+f"(d[3])
        : "r"(a[0]), "r"(a[1]), "r"(a[2]), "r"(a[3]), "r"(b0), "r"(b1));
}

// ---- pre-pass: K/V -> fragment-ordered fp16 (+ fused row-norm max) ----
__global__ __launch_bounds__(512)
void convert_kernel(const float* __restrict__ K, const float* __restrict__ V)
{
    __shared__ float ts[128][65];
    const int bh = blockIdx.x, kt = blockIdx.y, tid = threadIdx.x;
    const int lane = tid & 31;
    const size_t base = (size_t)bh * SEQ * DH + (size_t)kt * 128 * DH;

    // decomposition for fragment writes
    const int half = tid >> 8, rem = tid & 255;
    const int ks = rem >> 6, b = (rem >> 5) & 1, ln = rem & 31;
    const int g2 = ln >> 2, tg2 = ln & 3;
    uint32_t* outK = g_Kf + ((size_t)(bh * 8 + kt)) * 4096
                   + (size_t)(((half * 4 + ks) * 2 + b) * 256 + ln * 8);
    uint32_t* outV = g_Vf + ((size_t)(bh * 8 + kt)) * 4096
                   + (size_t)(((half * 4 + ks) * 2 + b) * 256 + ln * 8);

    // stage K fp32 + row-norm max
    float mxq = 0.f;
    #pragma unroll
    for (int n = 0; n < 4; n++) {
        int i = tid + n * 512;
        int r = i >> 4, c = (i & 15) * 4;
        float4 v = *(const float4*)(K + base + r * DH + c);
        ts[r][c] = v.x; ts[r][c+1] = v.y; ts[r][c+2] = v.z; ts[r][c+3] = v.w;
        float sq = v.x*v.x + v.y*v.y + v.z*v.z + v.w*v.w;
        #pragma unroll
        for (int o = 1; o <= 8; o <<= 1) sq += __shfl_xor_sync(0xffffffffu, sq, o);
        mxq = fmaxf(mxq, sq);
    }
    #pragma unroll
    for (int o = 16; o >= 1; o >>= 1) mxq = fmaxf(mxq, __shfl_xor_sync(0xffffffffu, mxq, o));
    if (lane == 0) atomicMax(&g_maxkq[bh], __float_as_uint(mxq));
    __syncthreads();

    // write K fragments: value = K[row][2w..2w+1], row = half*64+nt*8+g2, w = ks*8+b*4+tg2
    {
        uint32_t frag[8];
        #pragma unroll
        for (int nt = 0; nt < 8; nt++) {
            int r = half * 64 + nt * 8 + g2;
            int w = ks * 8 + b * 4 + tg2;
            frag[nt] = h2u(ts[r][2*w], ts[r][2*w + 1]);
        }
        *(uint4*)outK       = *(uint4*)&frag[0];
        *(uint4*)(outK + 4) = *(uint4*)&frag[4];
    }
    __syncthreads();

    // stage V fp32
    #pragma unroll
    for (int n = 0; n < 4; n++) {
        int i = tid + n * 512;
        int r = i >> 4, c = (i & 15) * 4;
        float4 v = *(const float4*)(V + base + r * DH + c);
        ts[r][c] = v.x; ts[r][c+1] = v.y; ts[r][c+2] = v.z; ts[r][c+3] = v.w;
    }
    __syncthreads();

    // write V^T fragments: value = h2(V[2kp][d], V[2kp+1][d]), d = nt*8+g2, kp = half*32+ks*8+b*4+tg2
    {
        uint32_t frag[8];
        int kp = half * 32 + ks * 8 + b * 4 + tg2;
        #pragma unroll
        for (int nt = 0; nt < 8; nt++) {
            int d = nt * 8 + g2;
            frag[nt] = h2u(ts[2*kp][d], ts[2*kp + 1][d]);
        }
        *(uint4*)outV       = *(uint4*)&frag[0];
        *(uint4*)(outV + 4) = *(uint4*)&frag[4];
    }
}

__global__ __launch_bounds__(NTHR, 2)
void relattn_mma(const float* __restrict__ Q, const float* __restrict__ PEK,
                 const float* __restrict__ PEV,
                 float* __restrict__ Out, float* __restrict__ Pout)
{
    extern __shared__ char sm8[];
    float*    sPST= (float*)(sm8 + OFF_PST);
    float*    qstg= (float*)(sm8 + OFF_PST);               // preamble overlay
    float*    sPEK= (float*)(sm8 + OFF_PST + 17408);       // preamble overlay
    float*    sQPE= (float*)(sm8 + OFF_QPE);
    float*    sPEV= (float*)(sm8 + OFF_PEV);
    float*    sM  = (float*)(sm8 + OFF_M);
    // tail overlays (p-stage dead)
    float*    sTap= (float*)(sm8 + OFF_PST);               // [64][34]
    float*    sLR = (float*)(sm8 + OFF_PST + 8704);        // [64][2]
    float*    sINV= (float*)(sm8 + OFF_PST + 9216);        // [64]
    float*    sOX = (float*)(sm8 + OFF_PST + 9472);        // O-exchange 18432B

    const int tid = threadIdx.x, lane = tid & 31, warp = tid >> 5;
    const int g = lane >> 2, tg = lane & 3;
    const int wm = warp & 3, wn = warp >> 2;               // 4 x 2 warp grid
    const int rm = wm * 16, cn = wn * 64, dn = wn * 32;

    const int bx = blockIdx.x;
    const int qblk = 15 - (bx >> 6);                       // longest first
    const int bh = bx & 63;
    const int q0 = qblk * NROW;
    const int ntiles = (q0 + NROW + 127) >> 7;

    const float* Qb = Q + (size_t)bh * SEQ * DH;
    const float maxk = sqrtf(__uint_as_float(g_maxkq[bh]));

    // ---- preamble: stage Q fp32 + pe tables ----
    #pragma unroll
    for (int n = 0; n < 4; n++) {
        int i = tid + n * NTHR;
        int r = i >> 4, c = (i & 15) * 4;
        *(float4*)(qstg + r * QSTG_STR + c) =
            *(const float4*)(Qb + (size_t)(q0 + r) * DH + c);
    }
    for (int i = tid; i < 33 * 16; i += NTHR) {
        int r = i >> 4, c = (i & 15) * 4;
        float4 a = *(const float4*)(PEK + r * DH + c);
        sPEK[r*66+c] = a.x; sPEK[r*66+c+1] = a.y; sPEK[r*66+c+2] = a.z; sPEK[r*66+c+3] = a.w;
        float4 b = *(const float4*)(PEV + r * DH + c);
        sPEV[r*66+c] = b.x; sPEV[r*66+c+1] = b.y; sPEV[r*66+c+2] = b.z; sPEV[r*66+c+3] = b.w;
    }
    __syncthreads();

    // ---- qpe[row][j] = q_row . pe_k[j] ----
    {
        int row = tid >> 2, quarter = tid & 3;
        const float* qr = qstg + row * QSTG_STR;
        int j0 = quarter * 8, jn = (quarter == 3) ? 9 : 8;
        #pragma unroll 1
        for (int jj = 0; jj < jn; jj++) {
            int j = j0 + jj;
            const float* pk = sPEK + j * 66;
            float a = 0.f;
            #pragma unroll
            for (int d = 0; d < 64; d++) a = fmaf(qr[d], pk[d], a);
            sQPE[row * 34 + j] = a;
        }
    }
    __syncthreads();

    // ---- M bound per row; Q fragments resident ----
    if (tid < NROW) {
        const float* qr = qstg + tid * QSTG_STR;
        float qn = 0.f;
        #pragma unroll
        for (int d = 0; d < 64; d++) qn = fmaf(qr[d], qr[d], qn);
        float mb = sQPE[tid * 34];
        #pragma unroll
        for (int j = 1; j < 33; j++) mb = fmaxf(mb, sQPE[tid * 34 + j]);
        sM[tid] = sqrtf(qn) * maxk + mb;
    }
    uint32_t qa[4][4];
    #pragma unroll
    for (int ks = 0; ks < 4; ks++) {
        const float* r0 = qstg + (rm + g) * QSTG_STR + 16*ks + 2*tg;
        const float* r1 = qstg + (rm + 8 + g) * QSTG_STR + 16*ks + 2*tg;
        qa[ks][0] = h2u(r0[0], r0[1]);
        qa[ks][1] = h2u(r1[0], r1[1]);
        qa[ks][2] = h2u(r0[8], r0[9]);
        qa[ks][3] = h2u(r1[8], r1[9]);
    }
    __syncthreads();

    float Mrow[2];
    #pragma unroll
    for (int s = 0; s < 2; s++) Mrow[s] = sM[rm + 8*s + g];

    // ================= main loop =================
    float lc[4] = {0.f, 0.f, 0.f, 0.f};
    float o[8][4] = {};

    for (int kt = 0; kt < ntiles; kt++) {
        __syncthreads();   // A: prior STS visible to all
        // stream out previous tile's p-stage (coalesced)
        if (kt > 0) {
            int ct = (kt - 1) * 128;
            #pragma unroll
            for (int j = 0; j < 8; j++) {
                int r = warp * 8 + j;
                float4 v = *(const float4*)(sPST + r * PST_STR + 4 * lane);
                *(float4*)(Pout + ((size_t)bh*SEQ + q0 + r)*SEQ + ct + 4*lane) = v;
            }
        }
        __syncthreads();   // B: stream-out done before new STS

        const bool live = (kt*128 + cn) <= (q0 + rm + 15);
        const uint32_t* Kf = g_Kf + ((size_t)(bh*8 + kt))*4096 + wn*2048 + lane*8;
        const uint32_t* Vf = g_Vf + ((size_t)(bh*8 + kt))*4096 + wn*2048 + lane*8;

        if (live) {
            const int ntmax = min(8, ((q0 + rm + 15 - kt*128 - cn) >> 3) + 1);
            const bool far = (kt*128 + cn + 63) <= (q0 + rm - 32);

            // ---- score: B-operands via coalesced LDG.128 from Kf ----
            float acc[8][4] = {};
            #pragma unroll
            for (int ks = 0; ks < 4; ks++) {
                uint4 b0a = *(const uint4*)(Kf + ks*512);
                uint4 b0b = *(const uint4*)(Kf + ks*512 + 4);
                uint4 b1a = *(const uint4*)(Kf + ks*512 + 256);
                uint4 b1b = *(const uint4*)(Kf + ks*512 + 260);
                const uint32_t* b0 = (const uint32_t*)&b0a;   // [0..3]=b0a, then b0b
                const uint32_t* b1 = (const uint32_t*)&b1a;
                #pragma unroll
                for (int nt = 0; nt < 8; nt++)
                    if (nt < ntmax) {
                        uint32_t w0 = (nt < 4) ? b0[nt] : ((const uint32_t*)&b0b)[nt-4];
                        uint32_t w1 = (nt < 4) ? b1[nt] : ((const uint32_t*)&b1b)[nt-4];
                        mma16(acc[nt], qa[ks], w0, w1);
                    }
            }

            uint32_t pa[4][4] = {};
            if (far) {
                float b0f = (sQPE[(rm + g) * 34]     - Mrow[0]) * ISD;
                float b1f = (sQPE[(rm + 8 + g) * 34] - Mrow[1]) * ISD;
                #pragma unroll
                for (int nt = 0; nt < 8; nt++) {
                    float p[4];
                    p[0] = __expf(fmaf(acc[nt][0], ISD, b0f));
                    p[1] = __expf(fmaf(acc[nt][1], ISD, b0f));
                    p[2] = __expf(fmaf(acc[nt][2], ISD, b1f));
                    p[3] = __expf(fmaf(acc[nt][3], ISD, b1f));
                    lc[0] += p[0]; lc[1] += p[1]; lc[2] += p[2]; lc[3] += p[3];
                    int cl = cn + 8*nt + 2*tg;
                    *(float2*)(sPST + (rm + g) * PST_STR + cl)     = make_float2(p[0], p[1]);
                    *(float2*)(sPST + (rm + 8 + g) * PST_STR + cl) = make_float2(p[2], p[3]);
                    int ki = nt >> 1;
                    if ((nt & 1) == 0) { pa[ki][0] = h2u(p[0], p[1]); pa[ki][1] = h2u(p[2], p[3]); }
                    else               { pa[ki][2] = h2u(p[0], p[1]); pa[ki][3] = h2u(p[2], p[3]); }
                }
            } else {
                #pragma unroll
                for (int nt = 0; nt < 8; nt++) {
                    if (nt < ntmax) {
                        float p[4];
                        #pragma unroll
                        for (int c = 0; c < 4; c++) {
                            int s = c >> 1;
                            int row = rm + 8*s + g;
                            int col = kt*128 + cn + 8*nt + 2*tg + (c&1);
                            int qg = q0 + row;
                            float v = NEGINF;
                            if (col <= qg) {
                                int j = col - qg + 32; j = j < 0 ? 0 : j;
                                v = acc[nt][c] + sQPE[row*34 + j];
                            }
                            float e = __expf((v - Mrow[s]) * ISD);
                            p[c] = e;
                            lc[c] += e;
                        }
                        int cl = cn + 8*nt + 2*tg;
                        *(float2*)(sPST + (rm + g) * PST_STR + cl)     = make_float2(p[0], p[1]);
                        *(float2*)(sPST + (rm + 8 + g) * PST_STR + cl) = make_float2(p[2], p[3]);
                        int ki = nt >> 1;
                        if ((nt & 1) == 0) { pa[ki][0] = h2u(p[0], p[1]); pa[ki][1] = h2u(p[2], p[3]); }
                        else               { pa[ki][2] = h2u(p[0], p[1]); pa[ki][3] = h2u(p[2], p[3]); }
                    } else {
                        float2 z = make_float2(0.f, 0.f);
                        int cl = cn + 8*nt + 2*tg;
                        *(float2*)(sPST + (rm + g) * PST_STR + cl)     = z;
                        *(float2*)(sPST + (rm + 8 + g) * PST_STR + cl) = z;
                    }
                }
            }

            // ---- PV: B-operands via coalesced LDG.128 from Vf ----
            #pragma unroll
            for (int ks = 0; ks < 4; ks++) {
                if (kt*128 + cn + 16*ks <= q0 + rm + 15) {
                    uint4 b0a = *(const uint4*)(Vf + ks*512);
                    uint4 b0b = *(const uint4*)(Vf + ks*512 + 4);
                    uint4 b1a = *(const uint4*)(Vf + ks*512 + 256);
                    uint4 b1b = *(const uint4*)(Vf + ks*512 + 260);
                    #pragma unroll
                    for (int nt = 0; nt < 8; nt++) {
                        uint32_t w0 = (nt < 4) ? ((const uint32_t*)&b0a)[nt] : ((const uint32_t*)&b0b)[nt-4];
                        uint32_t w1 = (nt < 4) ? ((const uint32_t*)&b1a)[nt] : ((const uint32_t*)&b1b)[nt-4];
                        mma16(o[nt], pa[ks], w0, w1);
                    }
                }
            }
        } else {
            float2 z = make_float2(0.f, 0.f);
            #pragma unroll
            for (int nt = 0; nt < 8; nt++) {
                int cl = cn + 8*nt + 2*tg;
                *(float2*)(sPST + (rm + g) * PST_STR + cl)     = z;
                *(float2*)(sPST + (rm + 8 + g) * PST_STR + cl) = z;
            }
        }
    }
    __syncthreads();   // all p-stage writes for last tile complete

    // ---- stream out final tile ----
    {
        int ct = (ntiles - 1) * 128;
        #pragma unroll
        for (int j = 0; j < 8; j++) {
            int r = warp * 8 + j;
            float4 v = *(const float4*)(sPST + r * PST_STR + 4 * lane);
            *(float4*)(Pout + ((size_t)bh*SEQ + q0 + r)*SEQ + ct + 4*lane) = v;
        }
    }
    float lloc[2] = { lc[0] + lc[1], lc[2] + lc[3] };
    #pragma unroll
    for (int s = 0; s < 2; s++) {
        lloc[s] += __shfl_xor_sync(0xffffffffu, lloc[s], 1);
        lloc[s] += __shfl_xor_sync(0xffffffffu, lloc[s], 2);
    }
    __syncthreads();   // stream-out visible; p-stage free for overlays

    // ---- taps from Pout (L2-hot), l partials, O-exchange ----
    {
        int row = tid >> 2, part = tid & 3;
        int qg = q0 + row;
        const float* Prow = Pout + ((size_t)bh*SEQ + qg)*SEQ;
        #pragma unroll
        for (int i = 0; i < 8; i++) {
            int j = part*8 + 1 + i;
            int col = qg - 32 + j;
            sTap[row*34 + j] = (col >= 0) ? Prow[col] : 0.f;
        }
    }
    if (tg == 0)
        #pragma unroll
        for (int s = 0; s < 2; s++)
            sLR[(rm + 8*s + g)*2 + wn] = lloc[s];
    {
        float* dst = sOX + wn*2304 + wm*576;
        #pragma unroll
        for (int j = 0; j < 4; j++) {
            int nt = 4*(1 - wn) + j;
            dst[g*36 + 8*j + 2*tg]         = o[nt][0];
            dst[g*36 + 8*j + 2*tg + 1]     = o[nt][1];
            dst[(g+8)*36 + 8*j + 2*tg]     = o[nt][2];
            dst[(g+8)*36 + 8*j + 2*tg + 1] = o[nt][3];
        }
    }
    __syncthreads();

    // ---- per-row l, w0 = l - sum(taps), inv ----
    if (tid < NROW) {
        float l = sLR[tid*2] + sLR[tid*2+1];
        float sum = 0.f;
        #pragma unroll
        for (int j = 1; j <= 32; j++) sum += sTap[tid*34 + j];
        sINV[tid] = 1.f / l;
        sTap[tid*34] = l - sum;   // raw w0
    }
    __syncthreads();

    // ---- combine O halves, normalize, rel-pos value epilogue ----
    float oo[4][4];
    {
        const float* src = sOX + (1 - wn)*2304 + wm*576;
        #pragma unroll
        for (int j = 0; j < 4; j++) {
            int nt = 4*wn + j;
            oo[j][0] = o[nt][0] + src[g*36 + 8*j + 2*tg];
            oo[j][1] = o[nt][1] + src[g*36 + 8*j + 2*tg + 1];
            oo[j][2] = o[nt][2] + src[(g+8)*36 + 8*j + 2*tg];
            oo[j][3] = o[nt][3] + src[(g+8)*36 + 8*j + 2*tg + 1];
        }
    }
    float invl[2] = { sINV[rm + g], sINV[rm + 8 + g] };
    #pragma unroll
    for (int nt = 0; nt < 4; nt++)
        #pragma unroll
        for (int c = 0; c < 4; c++)
            oo[nt][c] *= invl[c>>1];

    #pragma unroll 1
    for (int j = 0; j <= 32; j++) {
        float wj0 = sTap[(rm + g)*34 + j] * invl[0];
        float wj1 = sTap[(rm + 8 + g)*34 + j] * invl[1];
        #pragma unroll
        for (int nt = 0; nt < 4; nt++) {
            float pe0 = sPEV[j*66 + dn + 8*nt + 2*tg];
            float pe1 = sPEV[j*66 + dn + 8*nt + 2*tg + 1];
            oo[nt][0] = fmaf(wj0, pe0, oo[nt][0]);
            oo[nt][1] = fmaf(wj0, pe1, oo[nt][1]);
            oo[nt][2] = fmaf(wj1, pe0, oo[nt][2]);
            oo[nt][3] = fmaf(wj1, pe1, oo[nt][3]);
        }
    }

    // ---- write output ----
    #pragma unroll
    for (int nt = 0; nt < 4; nt++) {
        int rowL = rm + g, rowH = rm + 8 + g;
        int colb = dn + 8*nt + 2*tg;
        *(float2*)(Out + ((size_t)bh*SEQ + q0 + rowL)*DH + colb) = make_float2(oo[nt][0], oo[nt][1]);
        *(float2*)(Out + ((size_t)bh*SEQ + q0 + rowH)*DH + colb) = make_float2(oo[nt][2], oo[nt][3]);
    }

    // ---- in-place rescale of Pout (e -> p = e/l), L2-hot ----
    {
        const int cols = ntiles * 128;
        for (int r = warp; r < NROW; r += 8) {
            float inv = sINV[r];
            float4* rowp = (float4*)(Pout + ((size_t)bh*SEQ + q0 + r)*SEQ);
            for (int c4 = lane; c4 < (cols >> 2); c4 += 32) {
                float4 v = rowp[c4];
                v.x *= inv; v.y *= inv; v.z *= inv; v.w *= inv;
                rowp[c4] = v;
            }
        }
    }

    // ---- zero-fill masked p region ----
    int zc = SEQ - ntiles * 128;
    if (zc > 0) {
        int zq = zc >> 2;
        float4 z = make_float4(0.f, 0.f, 0.f, 0.f);
        float* base = Pout + ((size_t)bh*SEQ + q0)*SEQ + ntiles*128;
        for (int i = tid; i < NROW * zq; i += NTHR) {
            int r = i / zq, c = (i - r * zq) * 4;
            *(float4*)(base + (size_t)r * SEQ + c) = z;
        }
    }
}

extern "C" void kernel_launch(void* const* d_in, const int* in_sizes, int n_in,
                              void* d_out, int out_size)
{
    (void)in_sizes; (void)n_in; (void)out_size;
    const float* Q   = (const float*)d_in[0];
    const float* K   = (const float*)d_in[1];
    const float* V   = (const float*)d_in[2];
    const float* PEK = (const float*)d_in[3];
    const float* PEV = (const float*)d_in[4];
    float* Out  = (float*)d_out;
    float* Pout = Out + (size_t)BH * SEQ * DH;

    convert_kernel<<<dim3(BH, 8), 512>>>(K, V);
    cudaFuncSetAttribute(relattn_mma, cudaFuncAttributeMaxDynamicSharedMemorySize, SMEM_TOTAL);
    relattn_mma<<<1024, NTHR, SMEM_TOTAL>>>(Q, PEK, PEV, Out, Pout);
}

// round 13
// speedup vs baseline: 1.1082x; 1.1082x over previous
#include <cuda_runtime.h>
#include <cuda_fp16.h>
#include <math.h>
#include <stdint.h>

// B=4,H=16 -> BH=64; S=1024; D=64; rel-pos P=32
#define BH   64
#define SEQ  1024
#define DH   64
#define NTHR 256
#define NROW 64
#define ISD  0.125f
#define NEGINF (-INFINITY)

#define KW_STRW 36      // K fp16 tile stride (words); 144B/row
#define VT_STRW 68      // V^T fp16 tile stride (words); 272B/row
#define PST_STR 132     // p-stage stride (floats)
#define QSTG_STR 68     // fp32 Q staging stride

// smem layout (bytes)
#define OFF_K    0                       // K fp16 [128][72h]   18432
#define OFF_VT   18432                   // V^T fp16 [64][136h] 17408
#define OFF_PST  35840                   // p stage f32 [64][132] 33792 (preamble: Q f32 + pe_k; tail: taps/l/inv/OX)
#define OFF_QPE  69632                   // qpe [64][34] f32     8704
#define OFF_PEV  78336                   // pe_v [33][66] f32    8712
#define OFF_M    87048                   // M bound [64]          256
#define SMEM_TOTAL 87304

__device__ __align__(16) __half g_Kh[(size_t)BH * SEQ * DH];
__device__ __align__(16) __half g_Vth[(size_t)BH * DH * SEQ];   // [bh][d][k]
__device__ unsigned int g_maxkq[BH];    // max ||k_row||^2 bits (atomicMax, idempotent)

static __device__ __forceinline__ uint32_t h2u(float a, float b) {
    __half2 h = __floats2half2_rn(a, b);
    return *reinterpret_cast<uint32_t*>(&h);
}
static __device__ __forceinline__ void mma16(float* d, const uint32_t* a,
                                             uint32_t b0, uint32_t b1) {
    asm volatile("mma.sync.aligned.m16n8k16.row.col.f32.f16.f16.f32 "
        "{%0,%1,%2,%3},{%4,%5,%6,%7},{%8,%9},{%0,%1,%2,%3};"
        : "+f"(d[0]), "+f"(d[1]), "+f"(d[2]), "+f"(d[3])
        : "r"(a[0]), "r"(a[1]), "r"(a[2]), "r"(a[3]), "r"(b0), "r"(b1));
}
static __device__ __forceinline__ uint32_t smem_u32(const void* p) {
    uint32_t a;
    asm("{ .reg .u64 t; cvta.to.shared.u64 t, %1; cvt.u32.u64 %0, t; }" : "=r"(a) : "l"(p));
    return a;
}
static __device__ __forceinline__ void ldsm4(uint32_t& r0, uint32_t& r1,
                                             uint32_t& r2, uint32_t& r3, uint32_t addr) {
    asm volatile("ldmatrix.sync.aligned.m8n8.x4.shared.b16 {%0,%1,%2,%3}, [%4];"
        : "=r"(r0), "=r"(r1), "=r"(r2), "=r"(r3) : "r"(addr));
}

// ---- pre-pass: K -> fp16 (+ fused row-norm max), V -> fp16 transposed ----
__global__ __launch_bounds__(512)
void convert_kernel(const float* __restrict__ K, const float* __restrict__ V)
{
    __shared__ float ts[128][65];
    const int bh = blockIdx.x, kt = blockIdx.y, tid = threadIdx.x;
    const int lane = tid & 31;
    const size_t base = (size_t)bh * SEQ * DH + (size_t)kt * 128 * DH;

    const float4* Ks = (const float4*)(K + base);
    uint2* Kd = (uint2*)(g_Kh + base);
    float mxq = 0.f;
    #pragma unroll
    for (int n = 0; n < 4; n++) {
        int i = tid + n * 512;
        float4 v = Ks[i];
        uint2 u; u.x = h2u(v.x, v.y); u.y = h2u(v.z, v.w);
        Kd[i] = u;
        float sq = v.x*v.x + v.y*v.y + v.z*v.z + v.w*v.w;
        #pragma unroll
        for (int o = 1; o <= 8; o <<= 1) sq += __shfl_xor_sync(0xffffffffu, sq, o);
        mxq = fmaxf(mxq, sq);
    }
    #pragma unroll
    for (int o = 16; o >= 1; o >>= 1) mxq = fmaxf(mxq, __shfl_xor_sync(0xffffffffu, mxq, o));
    if (lane == 0) atomicMax(&g_maxkq[bh], __float_as_uint(mxq));

    #pragma unroll
    for (int n = 0; n < 4; n++) {
        int i = tid + n * 512;
        int r = i >> 4, c = (i & 15) * 4;
        float4 v = *(const float4*)(V + base + r * DH + c);
        ts[r][c] = v.x; ts[r][c+1] = v.y; ts[r][c+2] = v.z; ts[r][c+3] = v.w;
    }
    __syncthreads();
    __half* Vh = g_Vth + (size_t)bh * SEQ * DH + (size_t)kt * 128;
    #pragma unroll
    for (int n = 0; n < 2; n++) {
        int i = tid + n * 512;
        int d = i >> 4, c8 = (i & 15) * 8;
        __half hv[8];
        #pragma unroll
        for (int j = 0; j < 8; j++) hv[j] = __float2half_rn(ts[c8 + j][d]);
        *(uint4*)(Vh + (size_t)d * SEQ + c8) = *(uint4*)hv;
    }
}

__global__ __launch_bounds__(NTHR, 2)
void relattn_mma(const float* __restrict__ Q, const float* __restrict__ PEK,
                 const float* __restrict__ PEV,
                 float* __restrict__ Out, float* __restrict__ Pout)
{
    extern __shared__ char sm8[];
    uint32_t* kw  = (uint32_t*)(sm8 + OFF_K);
    uint32_t* vw  = (uint32_t*)(sm8 + OFF_VT);
    float*    sPST= (float*)(sm8 + OFF_PST);
    float*    qstg= (float*)(sm8 + OFF_PST);               // preamble overlay
    float*    sPEK= (float*)(sm8 + OFF_PST + 17408);       // preamble overlay
    float*    sQPE= (float*)(sm8 + OFF_QPE);
    float*    sPEV= (float*)(sm8 + OFF_PEV);
    float*    sM  = (float*)(sm8 + OFF_M);
    // tail overlays (p-stage dead)
    float*    sTap= (float*)(sm8 + OFF_PST);               // [64][34]
    float*    sLR = (float*)(sm8 + OFF_PST + 8704);        // [64][2]
    float*    sINV= (float*)(sm8 + OFF_PST + 9216);        // [64]
    float*    sOX = (float*)(sm8 + OFF_PST + 9472);        // O-exchange

    const int tid = threadIdx.x, lane = tid & 31, warp = tid >> 5;
    const int g = lane >> 2, tg = lane & 3;
    const int wm = warp & 3, wn = warp >> 2;               // 4 x 2 warp grid
    const int rm = wm * 16, cn = wn * 64, dn = wn * 32;

    const int bx = blockIdx.x;
    const int qblk = 15 - (bx >> 6);                       // longest first
    const int bh = bx & 63;
    const int q0 = qblk * NROW;
    const int ntiles = (q0 + NROW + 127) >> 7;

    const float* Qb = Q + (size_t)bh * SEQ * DH;
    const __half* Khb = g_Kh + (size_t)bh * SEQ * DH;
    const __half* Vthb = g_Vth + (size_t)bh * SEQ * DH;
    const float maxk = sqrtf(__uint_as_float(g_maxkq[bh]));

    // ldmatrix per-lane base addresses (x4: [nt0,b0],[nt0,b1],[nt0+1,b0],[nt0+1,b1])
    const int lrow = (lane & 7) + 8 * ((lane >> 4) & 1);   // row within nt-pair
    const int lb   = (lane >> 3) & 1;                      // b0/b1 (16B) select
    const uint32_t kbase = smem_u32(kw) + (uint32_t)(((cn + lrow) * KW_STRW + 4 * lb) * 4);
    const uint32_t vbase = smem_u32(vw) + (uint32_t)((lrow * VT_STRW + (cn >> 1) + 4 * lb) * 4);

    // ---- preamble: stage Q fp32 + pe tables ----
    #pragma unroll
    for (int n = 0; n < 4; n++) {
        int i = tid + n * NTHR;
        int r = i >> 4, c = (i & 15) * 4;
        *(float4*)(qstg + r * QSTG_STR + c) =
            *(const float4*)(Qb + (size_t)(q0 + r) * DH + c);
    }
    for (int i = tid; i < 33 * 16; i += NTHR) {
        int r = i >> 4, c = (i & 15) * 4;
        float4 a = *(const float4*)(PEK + r * DH + c);
        sPEK[r*66+c] = a.x; sPEK[r*66+c+1] = a.y; sPEK[r*66+c+2] = a.z; sPEK[r*66+c+3] = a.w;
        float4 b = *(const float4*)(PEV + r * DH + c);
        sPEV[r*66+c] = b.x; sPEV[r*66+c+1] = b.y; sPEV[r*66+c+2] = b.z; sPEV[r*66+c+3] = b.w;
    }
    __syncthreads();

    // ---- qpe[row][j] = q_row . pe_k[j] ----
    {
        int row = tid >> 2, quarter = tid & 3;
        const float* qr = qstg + row * QSTG_STR;
        int j0 = quarter * 8, jn = (quarter == 3) ? 9 : 8;
        #pragma unroll 1
        for (int jj = 0; jj < jn; jj++) {
            int j = j0 + jj;
            const float* pk = sPEK + j * 66;
            float a = 0.f;
            #pragma unroll
            for (int d = 0; d < 64; d++) a = fmaf(qr[d], pk[d], a);
            sQPE[row * 34 + j] = a;
        }
    }
    __syncthreads();

    // ---- M bound per row; Q fragments resident ----
    if (tid < NROW) {
        const float* qr = qstg + tid * QSTG_STR;
        float qn = 0.f;
        #pragma unroll
        for (int d = 0; d < 64; d++) qn = fmaf(qr[d], qr[d], qn);
        float mb = sQPE[tid * 34];
        #pragma unroll
        for (int j = 1; j < 33; j++) mb = fmaxf(mb, sQPE[tid * 34 + j]);
        sM[tid] = sqrtf(qn) * maxk + mb;
    }
    uint32_t qa[4][4];
    #pragma unroll
    for (int ks = 0; ks < 4; ks++) {
        const float* r0 = qstg + (rm + g) * QSTG_STR + 16*ks + 2*tg;
        const float* r1 = qstg + (rm + 8 + g) * QSTG_STR + 16*ks + 2*tg;
        qa[ks][0] = h2u(r0[0], r0[1]);
        qa[ks][1] = h2u(r1[0], r1[1]);
        qa[ks][2] = h2u(r0[8], r0[9]);
        qa[ks][3] = h2u(r1[8], r1[9]);
    }
    __syncthreads();

    float Mrow[2];
    #pragma unroll
    for (int s = 0; s < 2; s++) Mrow[s] = sM[rm + 8*s + g];

    // ================= main loop =================
    float lc[4] = {0.f, 0.f, 0.f, 0.f};
    float o[8][4] = {};

    for (int kt = 0; kt < ntiles; kt++) {
        // register prefetch of fp16 K/V (overlaps previous tile's PV/stream-out)
        uint4 kpre[4], vpre[4];
        #pragma unroll
        for (int n = 0; n < 4; n++) {
            int idx = tid + n * NTHR;
            int r = idx >> 3, c8 = (idx & 7) * 8;
            kpre[n] = *(const uint4*)(Khb + (size_t)(kt * 128 + r) * DH + c8);
        }
        #pragma unroll
        for (int n = 0; n < 4; n++) {
            int idx = tid + n * NTHR;
            int d = idx >> 4, c8 = (idx & 15) * 8;
            vpre[n] = *(const uint4*)(Vthb + (size_t)d * SEQ + kt * 128 + c8);
        }
        __syncthreads();   // A: all warps done reading kw/vw (prev tile)

        #pragma unroll
        for (int n = 0; n < 4; n++) {
            int idx = tid + n * NTHR;
            int r = idx >> 3;
            *(uint4*)(kw + r * KW_STRW + (idx & 7) * 4) = kpre[n];
        }
        #pragma unroll
        for (int n = 0; n < 4; n++) {
            int idx = tid + n * NTHR;
            int d = idx >> 4;
            *(uint4*)(vw + d * VT_STRW + (idx & 15) * 4) = vpre[n];
        }
        __syncthreads();   // B: tile staged

        const bool live = (kt*128 + cn) <= (q0 + rm + 15);

        if (live) {
            const int ntmax = min(8, ((q0 + rm + 15 - kt*128 - cn) >> 3) + 1);
            const bool far = (kt*128 + cn + 63) <= (q0 + rm - 32);

            // ---- score: B-frags via ldmatrix.x4 ----
            float acc[8][4] = {};
            #pragma unroll
            for (int ks = 0; ks < 4; ks++)
                #pragma unroll
                for (int p = 0; p < 4; p++) {
                    if (2*p < ntmax) {
                        uint32_t b0, b1, b2, b3;
                        ldsm4(b0, b1, b2, b3, kbase + (uint32_t)(p * 2304 + ks * 32));
                        mma16(acc[2*p], qa[ks], b0, b1);
                        if (2*p + 1 < ntmax) mma16(acc[2*p+1], qa[ks], b2, b3);
                    }
                }

            uint32_t pa[4][4] = {};
            if (far) {
                float b0f = (sQPE[(rm + g) * 34]     - Mrow[0]) * ISD;
                float b1f = (sQPE[(rm + 8 + g) * 34] - Mrow[1]) * ISD;
                #pragma unroll
                for (int nt = 0; nt < 8; nt++) {
                    float p[4];
                    p[0] = __expf(fmaf(acc[nt][0], ISD, b0f));
                    p[1] = __expf(fmaf(acc[nt][1], ISD, b0f));
                    p[2] = __expf(fmaf(acc[nt][2], ISD, b1f));
                    p[3] = __expf(fmaf(acc[nt][3], ISD, b1f));
                    lc[0] += p[0]; lc[1] += p[1]; lc[2] += p[2]; lc[3] += p[3];
                    int cl = cn + 8*nt + 2*tg;
                    *(float2*)(sPST + (rm + g) * PST_STR + cl)     = make_float2(p[0], p[1]);
                    *(float2*)(sPST + (rm + 8 + g) * PST_STR + cl) = make_float2(p[2], p[3]);
                    int ki = nt >> 1;
                    if ((nt & 1) == 0) { pa[ki][0] = h2u(p[0], p[1]); pa[ki][1] = h2u(p[2], p[3]); }
                    else               { pa[ki][2] = h2u(p[0], p[1]); pa[ki][3] = h2u(p[2], p[3]); }
                }
            } else {
                #pragma unroll
                for (int nt = 0; nt < 8; nt++) {
                    if (nt < ntmax) {
                        float p[4];
                        #pragma unroll
                        for (int c = 0; c < 4; c++) {
                            int s = c >> 1;
                            int row = rm + 8*s + g;
                            int col = kt*128 + cn + 8*nt + 2*tg + (c&1);
                            int qg = q0 + row;
                            float v = NEGINF;
                            if (col <= qg) {
                                int j = col - qg + 32; j = j < 0 ? 0 : j;
                                v = acc[nt][c] + sQPE[row*34 + j];
                            }
                            float e = __expf((v - Mrow[s]) * ISD);
                            p[c] = e;
                            lc[c] += e;
                        }
                        int cl = cn + 8*nt + 2*tg;
                        *(float2*)(sPST + (rm + g) * PST_STR + cl)     = make_float2(p[0], p[1]);
                        *(float2*)(sPST + (rm + 8 + g) * PST_STR + cl) = make_float2(p[2], p[3]);
                        int ki = nt >> 1;
                        if ((nt & 1) == 0) { pa[ki][0] = h2u(p[0], p[1]); pa[ki][1] = h2u(p[2], p[3]); }
                        else               { pa[ki][2] = h2u(p[0], p[1]); pa[ki][3] = h2u(p[2], p[3]); }
                    } else {
                        float2 z = make_float2(0.f, 0.f);
                        int cl = cn + 8*nt + 2*tg;
                        *(float2*)(sPST + (rm + g) * PST_STR + cl)     = z;
                        *(float2*)(sPST + (rm + 8 + g) * PST_STR + cl) = z;
                    }
                }
            }

            // ---- PV: B-frags via ldmatrix.x4, A from registers ----
            #pragma unroll
            for (int ks = 0; ks < 4; ks++) {
                if (kt*128 + cn + 16*ks <= q0 + rm + 15) {
                    #pragma unroll
                    for (int p = 0; p < 4; p++) {
                        uint32_t b0, b1, b2, b3;
                        ldsm4(b0, b1, b2, b3, vbase + (uint32_t)(p * 4352 + ks * 32));
                        mma16(o[2*p],   pa[ks], b0, b1);
                        mma16(o[2*p+1], pa[ks], b2, b3);
                    }
                }
            }
        } else {
            float2 z = make_float2(0.f, 0.f);
            #pragma unroll
            for (int nt = 0; nt < 8; nt++) {
                int cl = cn + 8*nt + 2*tg;
                *(float2*)(sPST + (rm + g) * PST_STR + cl)     = z;
                *(float2*)(sPST + (rm + 8 + g) * PST_STR + cl) = z;
            }
        }

        // ---- own-region stream-out (rows 16wm..+15, cols 64wn..+63): warp-local ----
        __syncwarp();
        {
            int ct = kt * 128 + cn;
            int c4 = (lane & 15) * 4;
            #pragma unroll
            for (int j = 0; j < 8; j++) {
                int r = rm + 2*j + (lane >> 4);
                float4 v = *(const float4*)(sPST + r * PST_STR + cn + c4);
                *(float4*)(Pout + ((size_t)bh*SEQ + q0 + r)*SEQ + ct + c4) = v;
            }
        }
    }
    __syncthreads();   // all stream-outs done; p-stage free for overlays

    // ---- l reduce ----
    float lloc[2] = { lc[0] + lc[1], lc[2] + lc[3] };
    #pragma unroll
    for (int s = 0; s < 2; s++) {
        lloc[s] += __shfl_xor_sync(0xffffffffu, lloc[s], 1);
        lloc[s] += __shfl_xor_sync(0xffffffffu, lloc[s], 2);
    }

    // ---- taps from Pout (L2-hot), l partials, O-exchange ----
    {
        int row = tid >> 2, part = tid & 3;
        int qg = q0 + row;
        const float* Prow = Pout + ((size_t)bh*SEQ + qg)*SEQ;
        #pragma unroll
        for (int i = 0; i < 8; i++) {
            int j = part*8 + 1 + i;
            int col = qg - 32 + j;
            sTap[row*34 + j] = (col >= 0) ? Prow[col] : 0.f;
        }
    }
    if (tg == 0)
        #pragma unroll
        for (int s = 0; s < 2; s++)
            sLR[(rm + 8*s + g)*2 + wn] = lloc[s];
    {
        float* dst = sOX + wn*2304 + wm*576;
        #pragma unroll
        for (int j = 0; j < 4; j++) {
            int nt = 4*(1 - wn) + j;
            dst[g*36 + 8*j + 2*tg]         = o[nt][0];
            dst[g*36 + 8*j + 2*tg + 1]     = o[nt][1];
            dst[(g+8)*36 + 8*j + 2*tg]     = o[nt][2];
            dst[(g+8)*36 + 8*j + 2*tg + 1] = o[nt][3];
        }
    }
    __syncthreads();

    // ---- per-row l, w0 = l - sum(taps), inv ----
    if (tid < NROW) {
        float l = sLR[tid*2] + sLR[tid*2+1];
        float sum = 0.f;
        #pragma unroll
        for (int j = 1; j <= 32; j++) sum += sTap[tid*34 + j];
        sINV[tid] = 1.f / l;
        sTap[tid*34] = l - sum;   // raw w0
    }
    __syncthreads();

    // ---- combine O halves, normalize, rel-pos value epilogue ----
    float oo[4][4];
    {
        const float* src = sOX + (1 - wn)*2304 + wm*576;
        #pragma unroll
        for (int j = 0; j < 4; j++) {
            int nt = 4*wn + j;
            oo[j][0] = o[nt][0] + src[g*36 + 8*j + 2*tg];
            oo[j][1] = o[nt][1] + src[g*36 + 8*j + 2*tg + 1];
            oo[j][2] = o[nt][2] + src[(g+8)*36 + 8*j + 2*tg];
            oo[j][3] = o[nt][3] + src[(g+8)*36 + 8*j + 2*tg + 1];
        }
    }
    float invl[2] = { sINV[rm + g], sINV[rm + 8 + g] };
    #pragma unroll
    for (int nt = 0; nt < 4; nt++)
        #pragma unroll
        for (int c = 0; c < 4; c++)
            oo[nt][c] *= invl[c>>1];

    #pragma unroll 1
    for (int j = 0; j <= 32; j++) {
        float wj0 = sTap[(rm + g)*34 + j] * invl[0];
        float wj1 = sTap[(rm + 8 + g)*34 + j] * invl[1];
        #pragma unroll
        for (int nt = 0; nt < 4; nt++) {
            float pe0 = sPEV[j*66 + dn + 8*nt + 2*tg];
            float pe1 = sPEV[j*66 + dn + 8*nt + 2*tg + 1];
            oo[nt][0] = fmaf(wj0, pe0, oo[nt][0]);
            oo[nt][1] = fmaf(wj0, pe1, oo[nt][1]);
            oo[nt][2] = fmaf(wj1, pe0, oo[nt][2]);
            oo[nt][3] = fmaf(wj1, pe1, oo[nt][3]);
        }
    }

    // ---- write output ----
    #pragma unroll
    for (int nt = 0; nt < 4; nt++) {
        int rowL = rm + g, rowH = rm + 8 + g;
        int colb = dn + 8*nt + 2*tg;
        *(float2*)(Out + ((size_t)bh*SEQ + q0 + rowL)*DH + colb) = make_float2(oo[nt][0], oo[nt][1]);
        *(float2*)(Out + ((size_t)bh*SEQ + q0 + rowH)*DH + colb) = make_float2(oo[nt][2], oo[nt][3]);
    }

    // ---- in-place rescale of Pout (e -> p = e/l), L2-hot ----
    {
        const int cols = ntiles * 128;
        for (int r = warp; r < NROW; r += 8) {
            float inv = sINV[r];
            float4* rowp = (float4*)(Pout + ((size_t)bh*SEQ + q0 + r)*SEQ);
            for (int c4 = lane; c4 < (cols >> 2); c4 += 32) {
                float4 v = rowp[c4];
                v.x *= inv; v.y *= inv; v.z *= inv; v.w *= inv;
                rowp[c4] = v;
            }
        }
    }

    // ---- zero-fill masked p region ----
    int zc = SEQ - ntiles * 128;
    if (zc > 0) {
        int zq = zc >> 2;
        float4 z = make_float4(0.f, 0.f, 0.f, 0.f);
        float* base = Pout + ((size_t)bh*SEQ + q0)*SEQ + ntiles*128;
        for (int i = tid; i < NROW * zq; i += NTHR) {
            int r = i / zq, c = (i - r * zq) * 4;
            *(float4*)(base + (size_t)r * SEQ + c) = z;
        }
    }
}

extern "C" void kernel_launch(void* const* d_in, const int* in_sizes, int n_in,
                              void* d_out, int out_size)
{
    (void)in_sizes; (void)n_in; (void)out_size;
    const float* Q   = (const float*)d_in[0];
    const float* K   = (const float*)d_in[1];
    const float* V   = (const float*)d_in[2];
    const float* PEK = (const float*)d_in[3];
    const float* PEV = (const float*)d_in[4];
    float* Out  = (float*)d_out;
    float* Pout = Out + (size_t)BH * SEQ * DH;

    convert_kernel<<<dim3(BH, 8), 512>>>(K, V);
    cudaFuncSetAttribute(relattn_mma, cudaFuncAttributeMaxDynamicSharedMemorySize, SMEM_TOTAL);
    relattn_mma<<<1024, NTHR, SMEM_TOTAL>>>(Q, PEK, PEV, Out, Pout);
}